// round 1
// baseline (speedup 1.0000x reference)
#include <cuda_runtime.h>
#include <cstdint>

// Problem shape (fixed by this dataset instance)
#define B_TOT 64
#define T_TOT 2048
#define D_DIM 256
#define U_DIM 256
#define M_TOT (B_TOT * T_TOT)   // 131072

// Scratch for the three projections: [3][M][U] fp32 = 402 MB.
// (No cudaMalloc allowed -> __device__ global.)
__device__ float g_proj[3ull * M_TOT * U_DIM];

// ---------------------------------------------------------------------------
// Kernel A: fp32 SGEMM  P[w] = X @ K_w   (bias added later in the scan)
//   X: [M, 256] row-major, K_w: [256, 256] row-major, P: [M, 256]
//   Tile: BM=128, BN=64, BK=16, 256 threads, 8x4 microtile, double-buffered.
//   gridDim.x = 12 (w = bx>>2, n-tile = bx&3), gridDim.y = M/128.
// ---------------------------------------------------------------------------
__global__ __launch_bounds__(256) void bru_gemm(
    const float* __restrict__ X,
    const float* __restrict__ Kz,
    const float* __restrict__ Kr,
    const float* __restrict__ Kh)
{
    __shared__ float As[2][16][128];
    __shared__ float Bs[2][16][64];

    const int w  = blockIdx.x >> 2;
    const int n0 = (blockIdx.x & 3) * 64;
    const int m0 = blockIdx.y * 128;
    const float* __restrict__ W = (w == 0) ? Kz : (w == 1) ? Kr : Kh;
    float* __restrict__ Out = g_proj + (size_t)w * M_TOT * U_DIM;

    const int tid = threadIdx.x;
    const int tx  = tid & 15;   // n micro index
    const int ty  = tid >> 4;   // m micro index

    // A tile: 128 rows x 16 k = 512 float4; each thread loads ids {tid, tid+256}
    const int ar0 = tid >> 2;
    const int ar1 = (tid + 256) >> 2;
    const int ac  = (tid & 3) * 4;      // k offset within tile (same for both ids)
    // B tile: 16 k x 64 n = 256 float4; 1 per thread
    const int bk = tid >> 4;
    const int bn = (tid & 15) * 4;

    const float* Arow0 = X + (size_t)(m0 + ar0) * D_DIM;
    const float* Arow1 = X + (size_t)(m0 + ar1) * D_DIM;

    // Prologue: stage 0 -> smem buffer 0
    {
        float4 a0 = *(const float4*)(Arow0 + ac);
        float4 a1 = *(const float4*)(Arow1 + ac);
        float4 b  = *(const float4*)(W + (size_t)bk * U_DIM + n0 + bn);
        As[0][ac + 0][ar0] = a0.x; As[0][ac + 1][ar0] = a0.y;
        As[0][ac + 2][ar0] = a0.z; As[0][ac + 3][ar0] = a0.w;
        As[0][ac + 0][ar1] = a1.x; As[0][ac + 1][ar1] = a1.y;
        As[0][ac + 2][ar1] = a1.z; As[0][ac + 3][ar1] = a1.w;
        *(float4*)&Bs[0][bk][bn] = b;
    }
    __syncthreads();

    float acc[8][4];
#pragma unroll
    for (int i = 0; i < 8; i++)
#pragma unroll
        for (int j = 0; j < 4; j++) acc[i][j] = 0.0f;

    float4 na0, na1, nb4;
#pragma unroll 1
    for (int kt = 0; kt < 16; kt++) {
        const int buf = kt & 1;
        const int k0n = (kt + 1) * 16;
        if (kt < 15) {
            na0 = *(const float4*)(Arow0 + k0n + ac);
            na1 = *(const float4*)(Arow1 + k0n + ac);
            nb4 = *(const float4*)(W + (size_t)(k0n + bk) * U_DIM + n0 + bn);
        }
#pragma unroll
        for (int k = 0; k < 16; k++) {
            float a[8], b[4];
            *(float4*)&a[0] = *(const float4*)&As[buf][k][ty * 8];
            *(float4*)&a[4] = *(const float4*)&As[buf][k][ty * 8 + 4];
            *(float4*)&b[0] = *(const float4*)&Bs[buf][k][tx * 4];
#pragma unroll
            for (int i = 0; i < 8; i++)
#pragma unroll
                for (int j = 0; j < 4; j++)
                    acc[i][j] = fmaf(a[i], b[j], acc[i][j]);
        }
        if (kt < 15) {
            const int nxt = buf ^ 1;
            As[nxt][ac + 0][ar0] = na0.x; As[nxt][ac + 1][ar0] = na0.y;
            As[nxt][ac + 2][ar0] = na0.z; As[nxt][ac + 3][ar0] = na0.w;
            As[nxt][ac + 0][ar1] = na1.x; As[nxt][ac + 1][ar1] = na1.y;
            As[nxt][ac + 2][ar1] = na1.z; As[nxt][ac + 3][ar1] = na1.w;
            *(float4*)&Bs[nxt][bk][bn] = nb4;
        }
        __syncthreads();
    }

#pragma unroll
    for (int i = 0; i < 8; i++) {
        float4 v = make_float4(acc[i][0], acc[i][1], acc[i][2], acc[i][3]);
        *(float4*)(Out + (size_t)(m0 + ty * 8 + i) * U_DIM + n0 + tx * 4) = v;
    }
}

// ---------------------------------------------------------------------------
// Kernel B: sequential scan over T. One thread per (b,u) lane, coalesced in u.
// 8-deep register prefetch queue (projection loads are independent of h).
// tanh/sigmoid via __expf + __fdividef (~1e-6 error, safe vs 1e-3 threshold
// with 2048-step error feedback).
// ---------------------------------------------------------------------------
__global__ __launch_bounds__(128) void bru_scan(
    const float* __restrict__ mz, const float* __restrict__ mr,
    const float* __restrict__ bz, const float* __restrict__ br,
    const float* __restrict__ bh,
    float* __restrict__ out)
{
    const int g = blockIdx.x * 128 + threadIdx.x;   // lane id in [0, 16384)
    const int u = g & (U_DIM - 1);
    const int b = g >> 8;

    const size_t base = (size_t)b * T_TOT * U_DIM + u;
    const float* __restrict__ pz = g_proj + base;
    const float* __restrict__ pr = g_proj + (size_t)1 * M_TOT * U_DIM + base;
    const float* __restrict__ ph = g_proj + (size_t)2 * M_TOT * U_DIM + base;
    float* __restrict__ po = out + base;

    const float vmz = mz[u], vmr = mr[u];
    const float vbz = bz[u], vbr = br[u], vbh = bh[u];

    const int PF = 8;
    float qz[PF], qr[PF], qh[PF];
#pragma unroll
    for (int i = 0; i < PF; i++) {
        qz[i] = pz[(size_t)i * U_DIM];
        qr[i] = pr[(size_t)i * U_DIM];
        qh[i] = ph[(size_t)i * U_DIM];
    }

    float h = 0.0f;
#pragma unroll 1
    for (int t0 = 0; t0 < T_TOT; t0 += PF) {
#pragma unroll
        for (int j = 0; j < PF; j++) {
            const int t = t0 + j;
            const float xz = qz[j] + vbz;
            const float xr = qr[j] + vbr;
            const float xh = qh[j] + vbh;

            // prefetch t + PF (clamped; tail values never consumed)
            int tp = t + PF;
            tp = (tp < T_TOT) ? tp : (T_TOT - 1);
            qz[j] = pz[(size_t)tp * U_DIM];
            qr[j] = pr[(size_t)tp * U_DIM];
            qh[j] = ph[(size_t)tp * U_DIM];

            // r = tanh(xr + h*mr) + 1 = 2 - 2/(exp(2a)+1)
            const float ar = fmaf(h, vmr, xr);
            const float er = __expf(2.0f * ar);
            const float r  = 2.0f - __fdividef(2.0f, er + 1.0f);

            // z = sigmoid(xz + h*mz)
            const float az = fmaf(h, vmz, xz);
            const float z  = __fdividef(1.0f, 1.0f + __expf(-az));

            // hh = tanh(xh + r*h)
            const float ah = fmaf(r, h, xh);
            const float eh = __expf(2.0f * ah);
            const float hh = 1.0f - __fdividef(2.0f, eh + 1.0f);

            // h' = (1-z)*hh + z*h
            h = fmaf(z, h - hh, hh);
            po[(size_t)t * U_DIM] = h;
        }
    }
}

// ---------------------------------------------------------------------------
extern "C" void kernel_launch(void* const* d_in, const int* in_sizes, int n_in,
                              void* d_out, int out_size)
{
    const float* x  = (const float*)d_in[0];
    const float* kz = (const float*)d_in[1];
    const float* kr = (const float*)d_in[2];
    const float* kh = (const float*)d_in[3];
    const float* mz = (const float*)d_in[4];
    const float* mr = (const float*)d_in[5];
    const float* bz = (const float*)d_in[6];
    const float* br = (const float*)d_in[7];
    const float* bh = (const float*)d_in[8];
    float* out = (float*)d_out;

    dim3 gg(12, M_TOT / 128);
    bru_gemm<<<gg, 256>>>(x, kz, kr, kh);
    bru_scan<<<(B_TOT * U_DIM) / 128, 128>>>(mz, mr, bz, br, bh, out);
}

// round 4
// speedup vs baseline: 1.6972x; 1.6972x over previous
#include <cuda_runtime.h>
#include <cuda_bf16.h>
#include <cstdint>

// Problem shape (fixed)
#define B_TOT 64
#define T_TOT 2048
#define D_DIM 256
#define U_DIM 256
#define M_TOT (B_TOT * T_TOT)   // 131072

// Scratch: projections [3][M][U] fp32 = 402 MB, weights transposed+split bf16.
__device__ float g_proj[3ull * M_TOT * U_DIM];
__device__ __nv_bfloat16 g_wt_hi[3 * U_DIM * D_DIM];   // [n=768][k=256]
__device__ __nv_bfloat16 g_wt_lo[3 * U_DIM * D_DIM];

// ---------------------------------------------------------------------------
// PTX helpers — base sm_103-safe only (cp.async, ldmatrix, mma.sync).
// ---------------------------------------------------------------------------
__device__ __forceinline__ uint32_t smem_u32(const void* p) {
    uint32_t a;
    asm("{ .reg .u64 t; cvta.to.shared.u64 t, %1; cvt.u32.u64 %0, t; }" : "=r"(a) : "l"(p));
    return a;
}

#define CP_ASYNC16(dst, src) \
    asm volatile("cp.async.cg.shared.global [%0], [%1], 16;" :: "r"(dst), "l"(src) : "memory")
#define CP_ASYNC_COMMIT()   asm volatile("cp.async.commit_group;" ::: "memory")
#define CP_ASYNC_WAIT_ALL() asm volatile("cp.async.wait_all;" ::: "memory")

#define LDMATRIX_X4(r0, r1, r2, r3, addr) \
    asm volatile("ldmatrix.sync.aligned.m8n8.x4.shared.b16 {%0,%1,%2,%3}, [%4];" \
                 : "=r"(r0), "=r"(r1), "=r"(r2), "=r"(r3) : "r"(addr))

__device__ __forceinline__ void mma_bf16(float* d, const uint32_t* a, const uint32_t* b) {
    asm volatile(
        "mma.sync.aligned.m16n8k16.row.col.f32.bf16.bf16.f32 "
        "{%0,%1,%2,%3}, {%4,%5,%6,%7}, {%8,%9}, {%0,%1,%2,%3};"
        : "+f"(d[0]), "+f"(d[1]), "+f"(d[2]), "+f"(d[3])
        : "r"(a[0]), "r"(a[1]), "r"(a[2]), "r"(a[3]), "r"(b[0]), "r"(b[1]));
}

__device__ __forceinline__ unsigned short bf16_bits(float f) {
    __nv_bfloat16 b = __float2bfloat16(f);
    return *reinterpret_cast<unsigned short*>(&b);
}

// ---------------------------------------------------------------------------
// Kernel 0: weight prep. Wt[n][k] = W[k][u] transposed, split into bf16 hi/lo.
// ---------------------------------------------------------------------------
__global__ __launch_bounds__(256) void bru_wprep(
    const float* __restrict__ kz, const float* __restrict__ kr, const float* __restrict__ kh)
{
    int i = blockIdx.x * 256 + threadIdx.x;       // [0, 768*256)
    int w = i >> 16;
    int k = (i >> 8) & 255;
    int u = i & 255;
    const float* W = (w == 0) ? kz : (w == 1) ? kr : kh;
    float v = W[k * 256 + u];
    __nv_bfloat16 hi = __float2bfloat16(v);
    float lo = v - __bfloat162float(hi);
    int n = w * 256 + u;
    g_wt_hi[n * 256 + k] = hi;
    g_wt_lo[n * 256 + k] = __float2bfloat16(lo);
}

// ---------------------------------------------------------------------------
// Kernel A: mma.sync bf16-split GEMM.  C[M,768] = X[M,256] @ Wt^T
//   BM=128, BN=128, BK=32, 256 thr, 8 warps (4m x 2n), warp tile m32 x n64.
//   3 passes: Ahi*Bhi + Ahi*Blo + Alo*Bhi, fp32 accum.
//   SMEM rows padded to 80 B (40 bf16) -> ldmatrix conflict-free.
// ---------------------------------------------------------------------------
#define BM 128
#define BN 128
#define BK 32
#define RS 40                        // row stride in bf16 elems (80 B)
#define TILE_B (128 * RS * 2)        // 10240 B per array
#define STAGE_B (4 * TILE_B)         // Ahi, Alo, Bhi, Blo = 40960 B
#define SMEM_SZ (2 * STAGE_B)        // 81920 B

__global__ __launch_bounds__(256) void bru_gemm_mma(const float* __restrict__ X)
{
    extern __shared__ char sm[];
    const uint32_t smb = smem_u32(sm);
    const int tid  = threadIdx.x;
    const int wid  = tid >> 5;
    const int lane = tid & 31;

    const int nt = blockIdx.x;            // 0..5 over N=768
    const int m0 = blockIdx.y * BM;
    const int n0 = nt * BN;

    const int wm = (wid >> 1) * 32;       // warp m offset in tile
    const int wn = (wid & 1) * 64;        // warp n offset in tile

    // stage base offsets (bytes): [stage][Ahi, Alo, Bhi, Blo]
    auto OA_HI = [&](int s) { return smb + s * STAGE_B; };
    auto OA_LO = [&](int s) { return smb + s * STAGE_B + TILE_B; };
    auto OB_HI = [&](int s) { return smb + s * STAGE_B + 2 * TILE_B; };
    auto OB_LO = [&](int s) { return smb + s * STAGE_B + 3 * TILE_B; };

    // ---- loaders ----
    // A: 128 rows x 32 fp32 = 1024 float4 / 256 thr = 4 each
    float4 areg[4];
    const int a_row = tid >> 1;                   // s/8 pattern: see below
    auto ldgA = [&](int c) {
        const int kc = c * BK;
#pragma unroll
        for (int i = 0; i < 4; i++) {
            int s = i * 256 + tid;
            int row = s >> 3, c4 = s & 7;
            areg[i] = *(const float4*)(X + (size_t)(m0 + row) * D_DIM + kc + c4 * 4);
        }
    };
    auto stsA = [&](int st) {
#pragma unroll
        for (int i = 0; i < 4; i++) {
            int s = i * 256 + tid;
            int row = s >> 3, c4 = s & 7;
            uint32_t off = (uint32_t)(row * (RS * 2) + c4 * 8);
            float f[4] = {areg[i].x, areg[i].y, areg[i].z, areg[i].w};
            unsigned short h[4], l[4];
#pragma unroll
            for (int j = 0; j < 4; j++) {
                h[j] = bf16_bits(f[j]);
                __nv_bfloat16 hb = *reinterpret_cast<__nv_bfloat16*>(&h[j]);
                l[j] = bf16_bits(f[j] - __bfloat162float(hb));
            }
            uint32_t ph0 = (uint32_t)h[0] | ((uint32_t)h[1] << 16);
            uint32_t ph1 = (uint32_t)h[2] | ((uint32_t)h[3] << 16);
            uint32_t pl0 = (uint32_t)l[0] | ((uint32_t)l[1] << 16);
            uint32_t pl1 = (uint32_t)l[2] | ((uint32_t)l[3] << 16);
            asm volatile("st.shared.v2.b32 [%0], {%1, %2};" :: "r"(OA_HI(st) + off), "r"(ph0), "r"(ph1) : "memory");
            asm volatile("st.shared.v2.b32 [%0], {%1, %2};" :: "r"(OA_LO(st) + off), "r"(pl0), "r"(pl1) : "memory");
        }
    };
    // B: 128 n-rows x 32 k bf16 per array = 512 x 16B / 256 thr = 2 each per array
    auto cpB = [&](int c, int st) {
        const int kc = c * BK;
#pragma unroll
        for (int i = 0; i < 2; i++) {
            int g = i * 256 + tid;
            int row = g >> 2, seg = g & 3;
            size_t e = (size_t)(n0 + row) * D_DIM + kc + seg * 8;
            uint32_t off = (uint32_t)(row * (RS * 2) + seg * 16);
            CP_ASYNC16(OB_HI(st) + off, (const char*)g_wt_hi + e * 2);
            CP_ASYNC16(OB_LO(st) + off, (const char*)g_wt_lo + e * 2);
        }
        CP_ASYNC_COMMIT();
    };

    // ---- prologue ----
    ldgA(0);
    cpB(0, 0);
    stsA(0);
    CP_ASYNC_WAIT_ALL();
    __syncthreads();

    float acc[2][8][4];
#pragma unroll
    for (int mi = 0; mi < 2; mi++)
#pragma unroll
        for (int ni = 0; ni < 8; ni++)
#pragma unroll
            for (int r = 0; r < 4; r++) acc[mi][ni][r] = 0.0f;

    // ldmatrix lane addressing: lane L -> row (L%16), col-half (L/16)*16B
    const int lrow = lane & 15;
    const int lhal = (lane >> 4) << 4;   // 0 or 16 bytes

    // ---- main loop over 8 K-chunks ----
    for (int c = 0; c < 8; c++) {
        const int st = c & 1;
        if (c < 7) { cpB(c + 1, st ^ 1); ldgA(c + 1); }

#pragma unroll
        for (int kk = 0; kk < 2; kk++) {          // two k16 steps per chunk
            const uint32_t kb = (uint32_t)(kk * 32);  // 16 bf16 = 32 B
            uint32_t ah[2][4], al[2][4], bh[4][4], bl[4][4];
#pragma unroll
            for (int mi = 0; mi < 2; mi++) {
                uint32_t ra = (uint32_t)((wm + mi * 16 + lrow) * (RS * 2)) + kb + lhal;
                LDMATRIX_X4(ah[mi][0], ah[mi][1], ah[mi][2], ah[mi][3], OA_HI(st) + ra);
                LDMATRIX_X4(al[mi][0], al[mi][1], al[mi][2], al[mi][3], OA_LO(st) + ra);
            }
#pragma unroll
            for (int nj = 0; nj < 4; nj++) {
                uint32_t rb = (uint32_t)((wn + nj * 16 + lrow) * (RS * 2)) + kb + lhal;
                LDMATRIX_X4(bh[nj][0], bh[nj][1], bh[nj][2], bh[nj][3], OB_HI(st) + rb);
                LDMATRIX_X4(bl[nj][0], bl[nj][1], bl[nj][2], bl[nj][3], OB_LO(st) + rb);
            }
#pragma unroll
            for (int mi = 0; mi < 2; mi++)
#pragma unroll
                for (int nj = 0; nj < 4; nj++) {
                    // n16 tile nj -> two n8 frags: {R0,R2} and {R1,R3}
                    uint32_t b0h[2] = {bh[nj][0], bh[nj][2]};
                    uint32_t b1h[2] = {bh[nj][1], bh[nj][3]};
                    uint32_t b0l[2] = {bl[nj][0], bl[nj][2]};
                    uint32_t b1l[2] = {bl[nj][1], bl[nj][3]};
                    mma_bf16(acc[mi][nj * 2 + 0], ah[mi], b0h);
                    mma_bf16(acc[mi][nj * 2 + 0], ah[mi], b0l);
                    mma_bf16(acc[mi][nj * 2 + 0], al[mi], b0h);
                    mma_bf16(acc[mi][nj * 2 + 1], ah[mi], b1h);
                    mma_bf16(acc[mi][nj * 2 + 1], ah[mi], b1l);
                    mma_bf16(acc[mi][nj * 2 + 1], al[mi], b1h);
                }
        }

        if (c < 7) {
            stsA(st ^ 1);
            CP_ASYNC_WAIT_ALL();
            __syncthreads();
        }
    }

    // ---- epilogue: direct float2 stores (32B-sector aligned quads) ----
    const int w = nt >> 1;                 // weight index 0..2
    const int u0 = (nt & 1) * BN;          // u offset within U=256
    float* Out = g_proj + (size_t)w * M_TOT * U_DIM;

    const int trow = lane >> 2;
    const int tcol = (lane & 3) * 2;
#pragma unroll
    for (int mi = 0; mi < 2; mi++)
#pragma unroll
        for (int ni = 0; ni < 8; ni++) {
            int r = m0 + wm + mi * 16 + trow;
            int cc = u0 + wn + ni * 8 + tcol;
            float2 v0 = make_float2(acc[mi][ni][0], acc[mi][ni][1]);
            float2 v1 = make_float2(acc[mi][ni][2], acc[mi][ni][3]);
            *(float2*)(Out + (size_t)r * U_DIM + cc) = v0;
            *(float2*)(Out + (size_t)(r + 8) * U_DIM + cc) = v1;
        }
}

// ---------------------------------------------------------------------------
// Kernel B: sequential scan over T (unchanged; known-good 360 us).
// ---------------------------------------------------------------------------
__global__ __launch_bounds__(128) void bru_scan(
    const float* __restrict__ mz, const float* __restrict__ mr,
    const float* __restrict__ bz, const float* __restrict__ br,
    const float* __restrict__ bh,
    float* __restrict__ out)
{
    const int g = blockIdx.x * 128 + threadIdx.x;
    const int u = g & (U_DIM - 1);
    const int b = g >> 8;

    const size_t base = (size_t)b * T_TOT * U_DIM + u;
    const float* __restrict__ pz = g_proj + base;
    const float* __restrict__ pr = g_proj + (size_t)1 * M_TOT * U_DIM + base;
    const float* __restrict__ ph = g_proj + (size_t)2 * M_TOT * U_DIM + base;
    float* __restrict__ po = out + base;

    const float vmz = mz[u], vmr = mr[u];
    const float vbz = bz[u], vbr = br[u], vbh = bh[u];

    const int PF = 8;
    float qz[PF], qr[PF], qh[PF];
#pragma unroll
    for (int i = 0; i < PF; i++) {
        qz[i] = pz[(size_t)i * U_DIM];
        qr[i] = pr[(size_t)i * U_DIM];
        qh[i] = ph[(size_t)i * U_DIM];
    }

    float h = 0.0f;
#pragma unroll 1
    for (int t0 = 0; t0 < T_TOT; t0 += PF) {
#pragma unroll
        for (int j = 0; j < PF; j++) {
            const int t = t0 + j;
            const float xz = qz[j] + vbz;
            const float xr = qr[j] + vbr;
            const float xh = qh[j] + vbh;

            int tp = t + PF;
            tp = (tp < T_TOT) ? tp : (T_TOT - 1);
            qz[j] = pz[(size_t)tp * U_DIM];
            qr[j] = pr[(size_t)tp * U_DIM];
            qh[j] = ph[(size_t)tp * U_DIM];

            const float ar = fmaf(h, vmr, xr);
            const float er = __expf(2.0f * ar);
            const float r  = 2.0f - __fdividef(2.0f, er + 1.0f);

            const float az = fmaf(h, vmz, xz);
            const float z  = __fdividef(1.0f, 1.0f + __expf(-az));

            const float ah = fmaf(r, h, xh);
            const float eh = __expf(2.0f * ah);
            const float hh = 1.0f - __fdividef(2.0f, eh + 1.0f);

            h = fmaf(z, h - hh, hh);
            po[(size_t)t * U_DIM] = h;
        }
    }
}

// ---------------------------------------------------------------------------
extern "C" void kernel_launch(void* const* d_in, const int* in_sizes, int n_in,
                              void* d_out, int out_size)
{
    const float* x  = (const float*)d_in[0];
    const float* kz = (const float*)d_in[1];
    const float* kr = (const float*)d_in[2];
    const float* kh = (const float*)d_in[3];
    const float* mz = (const float*)d_in[4];
    const float* mr = (const float*)d_in[5];
    const float* bz = (const float*)d_in[6];
    const float* br = (const float*)d_in[7];
    const float* bh = (const float*)d_in[8];
    float* out = (float*)d_out;

    cudaFuncSetAttribute(bru_gemm_mma, cudaFuncAttributeMaxDynamicSharedMemorySize, SMEM_SZ);

    bru_wprep<<<768, 256>>>(kz, kr, kh);
    dim3 gg(6, M_TOT / BM);
    bru_gemm_mma<<<gg, 256, SMEM_SZ>>>(x);
    bru_scan<<<(B_TOT * U_DIM) / 128, 128>>>(mz, mr, bz, br, bh, out);
}

// round 6
// speedup vs baseline: 1.7279x; 1.0181x over previous
#include <cuda_runtime.h>
#include <cuda_bf16.h>
#include <cstdint>

// Problem shape (fixed)
#define B_TOT 64
#define T_TOT 2048
#define D_DIM 256
#define U_DIM 256
#define M_TOT (B_TOT * T_TOT)   // 131072

// Scratch: projections [3][M][U] fp32 = 402 MB, weights transposed+split bf16.
__device__ float g_proj[3ull * M_TOT * U_DIM];
__device__ __nv_bfloat16 g_wt_hi[3 * U_DIM * D_DIM];   // [n=768][k=256]
__device__ __nv_bfloat16 g_wt_lo[3 * U_DIM * D_DIM];

// ---------------------------------------------------------------------------
// PTX helpers — base sm_103-safe only (cp.async, ldmatrix, mma.sync, mufu).
// ---------------------------------------------------------------------------
__device__ __forceinline__ uint32_t smem_u32(const void* p) {
    uint32_t a;
    asm("{ .reg .u64 t; cvta.to.shared.u64 t, %1; cvt.u32.u64 %0, t; }" : "=r"(a) : "l"(p));
    return a;
}

#define CP_ASYNC16(dst, src) \
    asm volatile("cp.async.cg.shared.global [%0], [%1], 16;" :: "r"(dst), "l"(src) : "memory")
#define CP_ASYNC_COMMIT()   asm volatile("cp.async.commit_group;" ::: "memory")
#define CP_ASYNC_WAIT_ALL() asm volatile("cp.async.wait_all;" ::: "memory")

#define LDMATRIX_X4(r0, r1, r2, r3, addr) \
    asm volatile("ldmatrix.sync.aligned.m8n8.x4.shared.b16 {%0,%1,%2,%3}, [%4];" \
                 : "=r"(r0), "=r"(r1), "=r"(r2), "=r"(r3) : "r"(addr))

__device__ __forceinline__ void mma_bf16(float* d, const uint32_t* a, const uint32_t* b) {
    asm volatile(
        "mma.sync.aligned.m16n8k16.row.col.f32.bf16.bf16.f32 "
        "{%0,%1,%2,%3}, {%4,%5,%6,%7}, {%8,%9}, {%0,%1,%2,%3};"
        : "+f"(d[0]), "+f"(d[1]), "+f"(d[2]), "+f"(d[3])
        : "r"(a[0]), "r"(a[1]), "r"(a[2]), "r"(a[3]), "r"(b[0]), "r"(b[1]));
}

__device__ __forceinline__ float ex2a(float x) {
    float y; asm("ex2.approx.f32 %0, %1;" : "=f"(y) : "f"(x)); return y;
}
__device__ __forceinline__ float rcpa(float x) {
    float y; asm("rcp.approx.f32 %0, %1;" : "=f"(y) : "f"(x)); return y;
}

__device__ __forceinline__ unsigned short bf16_bits(float f) {
    __nv_bfloat16 b = __float2bfloat16(f);
    return *reinterpret_cast<unsigned short*>(&b);
}

// ---------------------------------------------------------------------------
// Kernel 0: weight prep. Wt[n][k] = W[k][u] transposed, split into bf16 hi/lo.
// ---------------------------------------------------------------------------
__global__ __launch_bounds__(256) void bru_wprep(
    const float* __restrict__ kz, const float* __restrict__ kr, const float* __restrict__ kh)
{
    int i = blockIdx.x * 256 + threadIdx.x;       // [0, 768*256)
    int w = i >> 16;
    int k = (i >> 8) & 255;
    int u = i & 255;
    const float* W = (w == 0) ? kz : (w == 1) ? kr : kh;
    float v = W[k * 256 + u];
    __nv_bfloat16 hi = __float2bfloat16(v);
    float lo = v - __bfloat162float(hi);
    int n = w * 256 + u;
    g_wt_hi[n * 256 + k] = hi;
    g_wt_lo[n * 256 + k] = __float2bfloat16(lo);
}

// ---------------------------------------------------------------------------
// Kernel A: mma.sync bf16-split GEMM (unchanged from round 4; ~490 us).
// ---------------------------------------------------------------------------
#define BM 128
#define BN 128
#define BK 32
#define RS 40                        // row stride in bf16 elems (80 B)
#define TILE_B (128 * RS * 2)        // 10240 B per array
#define STAGE_B (4 * TILE_B)         // Ahi, Alo, Bhi, Blo = 40960 B
#define SMEM_SZ (2 * STAGE_B)        // 81920 B

__global__ __launch_bounds__(256) void bru_gemm_mma(const float* __restrict__ X)
{
    extern __shared__ char sm[];
    const uint32_t smb = smem_u32(sm);
    const int tid  = threadIdx.x;
    const int wid  = tid >> 5;
    const int lane = tid & 31;

    const int nt = blockIdx.x;            // 0..5 over N=768
    const int m0 = blockIdx.y * BM;
    const int n0 = nt * BN;

    const int wm = (wid >> 1) * 32;
    const int wn = (wid & 1) * 64;

    auto OA_HI = [&](int s) { return smb + s * STAGE_B; };
    auto OA_LO = [&](int s) { return smb + s * STAGE_B + TILE_B; };
    auto OB_HI = [&](int s) { return smb + s * STAGE_B + 2 * TILE_B; };
    auto OB_LO = [&](int s) { return smb + s * STAGE_B + 3 * TILE_B; };

    float4 areg[4];
    auto ldgA = [&](int c) {
        const int kc = c * BK;
#pragma unroll
        for (int i = 0; i < 4; i++) {
            int s = i * 256 + tid;
            int row = s >> 3, c4 = s & 7;
            areg[i] = *(const float4*)(X + (size_t)(m0 + row) * D_DIM + kc + c4 * 4);
        }
    };
    auto stsA = [&](int st) {
#pragma unroll
        for (int i = 0; i < 4; i++) {
            int s = i * 256 + tid;
            int row = s >> 3, c4 = s & 7;
            uint32_t off = (uint32_t)(row * (RS * 2) + c4 * 8);
            float f[4] = {areg[i].x, areg[i].y, areg[i].z, areg[i].w};
            unsigned short h[4], l[4];
#pragma unroll
            for (int j = 0; j < 4; j++) {
                h[j] = bf16_bits(f[j]);
                __nv_bfloat16 hb = *reinterpret_cast<__nv_bfloat16*>(&h[j]);
                l[j] = bf16_bits(f[j] - __bfloat162float(hb));
            }
            uint32_t ph0 = (uint32_t)h[0] | ((uint32_t)h[1] << 16);
            uint32_t ph1 = (uint32_t)h[2] | ((uint32_t)h[3] << 16);
            uint32_t pl0 = (uint32_t)l[0] | ((uint32_t)l[1] << 16);
            uint32_t pl1 = (uint32_t)l[2] | ((uint32_t)l[3] << 16);
            asm volatile("st.shared.v2.b32 [%0], {%1, %2};" :: "r"(OA_HI(st) + off), "r"(ph0), "r"(ph1) : "memory");
            asm volatile("st.shared.v2.b32 [%0], {%1, %2};" :: "r"(OA_LO(st) + off), "r"(pl0), "r"(pl1) : "memory");
        }
    };
    auto cpB = [&](int c, int st) {
        const int kc = c * BK;
#pragma unroll
        for (int i = 0; i < 2; i++) {
            int g = i * 256 + tid;
            int row = g >> 2, seg = g & 3;
            size_t e = (size_t)(n0 + row) * D_DIM + kc + seg * 8;
            uint32_t off = (uint32_t)(row * (RS * 2) + seg * 16);
            CP_ASYNC16(OB_HI(st) + off, (const char*)g_wt_hi + e * 2);
            CP_ASYNC16(OB_LO(st) + off, (const char*)g_wt_lo + e * 2);
        }
        CP_ASYNC_COMMIT();
    };

    ldgA(0);
    cpB(0, 0);
    stsA(0);
    CP_ASYNC_WAIT_ALL();
    __syncthreads();

    float acc[2][8][4];
#pragma unroll
    for (int mi = 0; mi < 2; mi++)
#pragma unroll
        for (int ni = 0; ni < 8; ni++)
#pragma unroll
            for (int r = 0; r < 4; r++) acc[mi][ni][r] = 0.0f;

    const int lrow = lane & 15;
    const int lhal = (lane >> 4) << 4;

    for (int c = 0; c < 8; c++) {
        const int st = c & 1;
        if (c < 7) { cpB(c + 1, st ^ 1); ldgA(c + 1); }

#pragma unroll
        for (int kk = 0; kk < 2; kk++) {
            const uint32_t kb = (uint32_t)(kk * 32);
            uint32_t ah[2][4], al[2][4], bh[4][4], bl[4][4];
#pragma unroll
            for (int mi = 0; mi < 2; mi++) {
                uint32_t ra = (uint32_t)((wm + mi * 16 + lrow) * (RS * 2)) + kb + lhal;
                LDMATRIX_X4(ah[mi][0], ah[mi][1], ah[mi][2], ah[mi][3], OA_HI(st) + ra);
                LDMATRIX_X4(al[mi][0], al[mi][1], al[mi][2], al[mi][3], OA_LO(st) + ra);
            }
#pragma unroll
            for (int nj = 0; nj < 4; nj++) {
                uint32_t rb = (uint32_t)((wn + nj * 16 + lrow) * (RS * 2)) + kb + lhal;
                LDMATRIX_X4(bh[nj][0], bh[nj][1], bh[nj][2], bh[nj][3], OB_HI(st) + rb);
                LDMATRIX_X4(bl[nj][0], bl[nj][1], bl[nj][2], bl[nj][3], OB_LO(st) + rb);
            }
#pragma unroll
            for (int mi = 0; mi < 2; mi++)
#pragma unroll
                for (int nj = 0; nj < 4; nj++) {
                    uint32_t b0h[2] = {bh[nj][0], bh[nj][2]};
                    uint32_t b1h[2] = {bh[nj][1], bh[nj][3]};
                    uint32_t b0l[2] = {bl[nj][0], bl[nj][2]};
                    uint32_t b1l[2] = {bl[nj][1], bl[nj][3]};
                    mma_bf16(acc[mi][nj * 2 + 0], ah[mi], b0h);
                    mma_bf16(acc[mi][nj * 2 + 0], ah[mi], b0l);
                    mma_bf16(acc[mi][nj * 2 + 0], al[mi], b0h);
                    mma_bf16(acc[mi][nj * 2 + 1], ah[mi], b1h);
                    mma_bf16(acc[mi][nj * 2 + 1], ah[mi], b1l);
                    mma_bf16(acc[mi][nj * 2 + 1], al[mi], b1h);
                }
        }

        if (c < 7) {
            stsA(st ^ 1);
            CP_ASYNC_WAIT_ALL();
            __syncthreads();
        }
    }

    const int w = nt >> 1;
    const int u0 = (nt & 1) * BN;
    float* Out = g_proj + (size_t)w * M_TOT * U_DIM;

    const int trow = lane >> 2;
    const int tcol = (lane & 3) * 2;
#pragma unroll
    for (int mi = 0; mi < 2; mi++)
#pragma unroll
        for (int ni = 0; ni < 8; ni++) {
            int r = m0 + wm + mi * 16 + trow;
            int cc = u0 + wn + ni * 8 + tcol;
            float2 v0 = make_float2(acc[mi][ni][0], acc[mi][ni][1]);
            float2 v1 = make_float2(acc[mi][ni][2], acc[mi][ni][3]);
            *(float2*)(Out + (size_t)r * U_DIM + cc) = v0;
            *(float2*)(Out + (size_t)(r + 8) * U_DIM + cc) = v1;
        }
}

// ---------------------------------------------------------------------------
// Kernel B: sequential scan, rebuilt.
//   64 blocks x 256 threads: block = batch b, thread = u lane.
//   -> 1 block/SM, 2 warps/SMSP: MUFU-bound == chain-bound ~96 cyc/step.
//   exp2-domain math: biases/gains pre-scaled by 2*log2(e) / -log2(e);
//   raw ex2.approx + rcp.approx (same HW ops as __expf/__fdividef).
//   8-deep prefetch, clamp-free main loop + tail.
// ---------------------------------------------------------------------------
#define PF 8

__global__ __launch_bounds__(256) void bru_scan(
    const float* __restrict__ mz, const float* __restrict__ mr,
    const float* __restrict__ bz, const float* __restrict__ br,
    const float* __restrict__ bh,
    float* __restrict__ out)
{
    const int b = blockIdx.x;        // batch
    const int u = threadIdx.x;       // unit

    const size_t base = (size_t)b * T_TOT * U_DIM + u;
    const float* __restrict__ pz = g_proj + base;
    const float* __restrict__ pr = g_proj + (size_t)1 * M_TOT * U_DIM + base;
    const float* __restrict__ ph = g_proj + (size_t)2 * M_TOT * U_DIM + base;
    float* __restrict__ po = out + base;

    const float C2 = 2.8853900817779268f;    // 2*log2(e)
    const float CN = -1.4426950408889634f;   // -log2(e)

    const float mr2 = mr[u] * C2, br2 = br[u] * C2;   // r-path, exp2 domain
    const float mzn = mz[u] * CN, bzn = bz[u] * CN;   // z-path, exp2 domain
    const float bh2 = bh[u] * C2;                     // h-path, exp2 domain

    float qz[PF], qr[PF], qh[PF];
#pragma unroll
    for (int j = 0; j < PF; j++) {
        qz[j] = pz[(size_t)j * U_DIM];
        qr[j] = pr[(size_t)j * U_DIM];
        qh[j] = ph[(size_t)j * U_DIM];
    }

    float h = 0.0f;

#pragma unroll 1
    for (int t0 = 0; t0 < T_TOT - PF; t0 += PF) {
#pragma unroll
        for (int j = 0; j < PF; j++) {
            const float vz = qz[j], vr = qr[j], vh = qh[j];
            // prefetch step t0 + j + PF (never OOB in this loop)
            qz[j] = pz[(size_t)(j + PF) * U_DIM];
            qr[j] = pr[(size_t)(j + PF) * U_DIM];
            qh[j] = ph[(size_t)(j + PF) * U_DIM];

            // r = tanh(xr + h*mr) + 1 = 2 - 2/(exp2(ar2)+1)
            const float ar2 = fmaf(h, mr2, fmaf(vr, C2, br2));
            const float tr  = rcpa(ex2a(ar2) + 1.0f);
            const float r   = fmaf(-2.0f, tr, 2.0f);

            // z = sigmoid(xz + h*mz) = 1/(1 + exp2(azn))
            const float azn = fmaf(h, mzn, fmaf(vz, CN, bzn));
            const float z   = rcpa(ex2a(azn) + 1.0f);

            // hh = tanh(xh + r*h) = 1 - 2/(exp2(ah2)+1)
            const float hs  = h * C2;
            const float ah2 = fmaf(r, hs, fmaf(vh, C2, bh2));
            const float th  = rcpa(ex2a(ah2) + 1.0f);
            const float hh  = fmaf(-2.0f, th, 1.0f);

            h = fmaf(z, h - hh, hh);
            po[(size_t)j * U_DIM] = h;
        }
        pz += PF * U_DIM; pr += PF * U_DIM; ph += PF * U_DIM; po += PF * U_DIM;
    }

    // tail: last PF steps, no prefetch
#pragma unroll
    for (int j = 0; j < PF; j++) {
        const float ar2 = fmaf(h, mr2, fmaf(qr[j], C2, br2));
        const float tr  = rcpa(ex2a(ar2) + 1.0f);
        const float r   = fmaf(-2.0f, tr, 2.0f);

        const float azn = fmaf(h, mzn, fmaf(qz[j], CN, bzn));
        const float z   = rcpa(ex2a(azn) + 1.0f);

        const float hs  = h * C2;
        const float ah2 = fmaf(r, hs, fmaf(qh[j], C2, bh2));
        const float th  = rcpa(ex2a(ah2) + 1.0f);
        const float hh  = fmaf(-2.0f, th, 1.0f);

        h = fmaf(z, h - hh, hh);
        po[(size_t)j * U_DIM] = h;
    }
}

// ---------------------------------------------------------------------------
extern "C" void kernel_launch(void* const* d_in, const int* in_sizes, int n_in,
                              void* d_out, int out_size)
{
    const float* x  = (const float*)d_in[0];
    const float* kz = (const float*)d_in[1];
    const float* kr = (const float*)d_in[2];
    const float* kh = (const float*)d_in[3];
    const float* mz = (const float*)d_in[4];
    const float* mr = (const float*)d_in[5];
    const float* bz = (const float*)d_in[6];
    const float* br = (const float*)d_in[7];
    const float* bh = (const float*)d_in[8];
    float* out = (float*)d_out;

    cudaFuncSetAttribute(bru_gemm_mma, cudaFuncAttributeMaxDynamicSharedMemorySize, SMEM_SZ);

    bru_wprep<<<768, 256>>>(kz, kr, kh);
    dim3 gg(6, M_TOT / BM);
    bru_gemm_mma<<<gg, 256, SMEM_SZ>>>(x);
    bru_scan<<<B_TOT, 256>>>(mz, mr, bz, br, bh, out);
}

// round 10
// speedup vs baseline: 1.8779x; 1.0868x over previous
#include <cuda_runtime.h>
#include <cuda_bf16.h>
#include <cstdint>

// Problem shape (fixed)
#define B_TOT 64
#define T_TOT 2048
#define D_DIM 256
#define U_DIM 256
#define M_TOT (B_TOT * T_TOT)   // 131072

// Scratch: projections [3][M][U] fp32 = 402 MB, weights transposed+split bf16.
__device__ float g_proj[3ull * M_TOT * U_DIM];
__device__ __nv_bfloat16 g_wt_hi[3 * U_DIM * D_DIM];   // [n=768][k=256]
__device__ __nv_bfloat16 g_wt_lo[3 * U_DIM * D_DIM];

// ---------------------------------------------------------------------------
// PTX helpers — base sm_103-safe only (cp.async, ldmatrix, mma.sync, mufu).
// ---------------------------------------------------------------------------
__device__ __forceinline__ uint32_t smem_u32(const void* p) {
    uint32_t a;
    asm("{ .reg .u64 t; cvta.to.shared.u64 t, %1; cvt.u32.u64 %0, t; }" : "=r"(a) : "l"(p));
    return a;
}

#define CP_ASYNC16(dst, src) \
    asm volatile("cp.async.cg.shared.global [%0], [%1], 16;" :: "r"(dst), "l"(src) : "memory")
#define CP_ASYNC_COMMIT()   asm volatile("cp.async.commit_group;" ::: "memory")
#define CP_ASYNC_WAIT_ALL() asm volatile("cp.async.wait_all;" ::: "memory")

#define LDMATRIX_X4(r0, r1, r2, r3, addr) \
    asm volatile("ldmatrix.sync.aligned.m8n8.x4.shared.b16 {%0,%1,%2,%3}, [%4];" \
                 : "=r"(r0), "=r"(r1), "=r"(r2), "=r"(r3) : "r"(addr))

__device__ __forceinline__ void mma_bf16(float* d, const uint32_t* a, const uint32_t* b) {
    asm volatile(
        "mma.sync.aligned.m16n8k16.row.col.f32.bf16.bf16.f32 "
        "{%0,%1,%2,%3}, {%4,%5,%6,%7}, {%8,%9}, {%0,%1,%2,%3};"
        : "+f"(d[0]), "+f"(d[1]), "+f"(d[2]), "+f"(d[3])
        : "r"(a[0]), "r"(a[1]), "r"(a[2]), "r"(a[3]), "r"(b[0]), "r"(b[1]));
}

__device__ __forceinline__ float ex2a(float x) {
    float y; asm("ex2.approx.f32 %0, %1;" : "=f"(y) : "f"(x)); return y;
}
__device__ __forceinline__ float rcpa(float x) {
    float y; asm("rcp.approx.f32 %0, %1;" : "=f"(y) : "f"(x)); return y;
}

__device__ __forceinline__ unsigned short bf16_bits(float f) {
    __nv_bfloat16 b = __float2bfloat16(f);
    return *reinterpret_cast<unsigned short*>(&b);
}

// ---------------------------------------------------------------------------
// Kernel 0: weight prep. Wt[n][k] = W[k][u] transposed, split into bf16 hi/lo.
// ---------------------------------------------------------------------------
__global__ __launch_bounds__(256) void bru_wprep(
    const float* __restrict__ kz, const float* __restrict__ kr, const float* __restrict__ kh)
{
    int i = blockIdx.x * 256 + threadIdx.x;       // [0, 768*256)
    int w = i >> 16;
    int k = (i >> 8) & 255;
    int u = i & 255;
    const float* W = (w == 0) ? kz : (w == 1) ? kr : kh;
    float v = W[k * 256 + u];
    __nv_bfloat16 hi = __float2bfloat16(v);
    float lo = v - __bfloat162float(hi);
    int n = w * 256 + u;
    g_wt_hi[n * 256 + k] = hi;
    g_wt_lo[n * 256 + k] = __float2bfloat16(lo);
}

// ---------------------------------------------------------------------------
// Kernel A: mma.sync bf16-split GEMM (unchanged; ~490 us measured).
// ---------------------------------------------------------------------------
#define BM 128
#define BN 128
#define BK 32
#define RS 40                        // row stride in bf16 elems (80 B)
#define TILE_B (128 * RS * 2)        // 10240 B per array
#define STAGE_B (4 * TILE_B)         // Ahi, Alo, Bhi, Blo = 40960 B
#define SMEM_SZ (2 * STAGE_B)        // 81920 B

__global__ __launch_bounds__(256) void bru_gemm_mma(const float* __restrict__ X)
{
    extern __shared__ char sm[];
    const uint32_t smb = smem_u32(sm);
    const int tid  = threadIdx.x;
    const int wid  = tid >> 5;
    const int lane = tid & 31;

    const int nt = blockIdx.x;            // 0..5 over N=768
    const int m0 = blockIdx.y * BM;
    const int n0 = nt * BN;

    const int wm = (wid >> 1) * 32;
    const int wn = (wid & 1) * 64;

    auto OA_HI = [&](int s) { return smb + s * STAGE_B; };
    auto OA_LO = [&](int s) { return smb + s * STAGE_B + TILE_B; };
    auto OB_HI = [&](int s) { return smb + s * STAGE_B + 2 * TILE_B; };
    auto OB_LO = [&](int s) { return smb + s * STAGE_B + 3 * TILE_B; };

    float4 areg[4];
    auto ldgA = [&](int c) {
        const int kc = c * BK;
#pragma unroll
        for (int i = 0; i < 4; i++) {
            int s = i * 256 + tid;
            int row = s >> 3, c4 = s & 7;
            areg[i] = *(const float4*)(X + (size_t)(m0 + row) * D_DIM + kc + c4 * 4);
        }
    };
    auto stsA = [&](int st) {
#pragma unroll
        for (int i = 0; i < 4; i++) {
            int s = i * 256 + tid;
            int row = s >> 3, c4 = s & 7;
            uint32_t off = (uint32_t)(row * (RS * 2) + c4 * 8);
            float f[4] = {areg[i].x, areg[i].y, areg[i].z, areg[i].w};
            unsigned short h[4], l[4];
#pragma unroll
            for (int j = 0; j < 4; j++) {
                h[j] = bf16_bits(f[j]);
                __nv_bfloat16 hb = *reinterpret_cast<__nv_bfloat16*>(&h[j]);
                l[j] = bf16_bits(f[j] - __bfloat162float(hb));
            }
            uint32_t ph0 = (uint32_t)h[0] | ((uint32_t)h[1] << 16);
            uint32_t ph1 = (uint32_t)h[2] | ((uint32_t)h[3] << 16);
            uint32_t pl0 = (uint32_t)l[0] | ((uint32_t)l[1] << 16);
            uint32_t pl1 = (uint32_t)l[2] | ((uint32_t)l[3] << 16);
            asm volatile("st.shared.v2.b32 [%0], {%1, %2};" :: "r"(OA_HI(st) + off), "r"(ph0), "r"(ph1) : "memory");
            asm volatile("st.shared.v2.b32 [%0], {%1, %2};" :: "r"(OA_LO(st) + off), "r"(pl0), "r"(pl1) : "memory");
        }
    };
    auto cpB = [&](int c, int st) {
        const int kc = c * BK;
#pragma unroll
        for (int i = 0; i < 2; i++) {
            int g = i * 256 + tid;
            int row = g >> 2, seg = g & 3;
            size_t e = (size_t)(n0 + row) * D_DIM + kc + seg * 8;
            uint32_t off = (uint32_t)(row * (RS * 2) + seg * 16);
            CP_ASYNC16(OB_HI(st) + off, (const char*)g_wt_hi + e * 2);
            CP_ASYNC16(OB_LO(st) + off, (const char*)g_wt_lo + e * 2);
        }
        CP_ASYNC_COMMIT();
    };

    ldgA(0);
    cpB(0, 0);
    stsA(0);
    CP_ASYNC_WAIT_ALL();
    __syncthreads();

    float acc[2][8][4];
#pragma unroll
    for (int mi = 0; mi < 2; mi++)
#pragma unroll
        for (int ni = 0; ni < 8; ni++)
#pragma unroll
            for (int r = 0; r < 4; r++) acc[mi][ni][r] = 0.0f;

    const int lrow = lane & 15;
    const int lhal = (lane >> 4) << 4;

    for (int c = 0; c < 8; c++) {
        const int st = c & 1;
        if (c < 7) { cpB(c + 1, st ^ 1); ldgA(c + 1); }

#pragma unroll
        for (int kk = 0; kk < 2; kk++) {
            const uint32_t kb = (uint32_t)(kk * 32);
            uint32_t ah[2][4], al[2][4], bh[4][4], bl[4][4];
#pragma unroll
            for (int mi = 0; mi < 2; mi++) {
                uint32_t ra = (uint32_t)((wm + mi * 16 + lrow) * (RS * 2)) + kb + lhal;
                LDMATRIX_X4(ah[mi][0], ah[mi][1], ah[mi][2], ah[mi][3], OA_HI(st) + ra);
                LDMATRIX_X4(al[mi][0], al[mi][1], al[mi][2], al[mi][3], OA_LO(st) + ra);
            }
#pragma unroll
            for (int nj = 0; nj < 4; nj++) {
                uint32_t rb = (uint32_t)((wn + nj * 16 + lrow) * (RS * 2)) + kb + lhal;
                LDMATRIX_X4(bh[nj][0], bh[nj][1], bh[nj][2], bh[nj][3], OB_HI(st) + rb);
                LDMATRIX_X4(bl[nj][0], bl[nj][1], bl[nj][2], bl[nj][3], OB_LO(st) + rb);
            }
#pragma unroll
            for (int mi = 0; mi < 2; mi++)
#pragma unroll
                for (int nj = 0; nj < 4; nj++) {
                    uint32_t b0h[2] = {bh[nj][0], bh[nj][2]};
                    uint32_t b1h[2] = {bh[nj][1], bh[nj][3]};
                    uint32_t b0l[2] = {bl[nj][0], bl[nj][2]};
                    uint32_t b1l[2] = {bl[nj][1], bl[nj][3]};
                    mma_bf16(acc[mi][nj * 2 + 0], ah[mi], b0h);
                    mma_bf16(acc[mi][nj * 2 + 0], ah[mi], b0l);
                    mma_bf16(acc[mi][nj * 2 + 0], al[mi], b0h);
                    mma_bf16(acc[mi][nj * 2 + 1], ah[mi], b1h);
                    mma_bf16(acc[mi][nj * 2 + 1], ah[mi], b1l);
                    mma_bf16(acc[mi][nj * 2 + 1], al[mi], b1h);
                }
        }

        if (c < 7) {
            stsA(st ^ 1);
            CP_ASYNC_WAIT_ALL();
            __syncthreads();
        }
    }

    const int w = nt >> 1;
    const int u0 = (nt & 1) * BN;
    float* Out = g_proj + (size_t)w * M_TOT * U_DIM;

    const int trow = lane >> 2;
    const int tcol = (lane & 3) * 2;
#pragma unroll
    for (int mi = 0; mi < 2; mi++)
#pragma unroll
        for (int ni = 0; ni < 8; ni++) {
            int r = m0 + wm + mi * 16 + trow;
            int cc = u0 + wn + ni * 8 + tcol;
            float2 v0 = make_float2(acc[mi][ni][0], acc[mi][ni][1]);
            float2 v1 = make_float2(acc[mi][ni][2], acc[mi][ni][3]);
            *(float2*)(Out + (size_t)r * U_DIM + cc) = v0;
            *(float2*)(Out + (size_t)(r + 8) * U_DIM + cc) = v1;
        }
}

// ---------------------------------------------------------------------------
// Kernel B: sequential scan.  PF=16 register prefetch (48 outstanding LDGs
// per warp, under the ~55 per-warp cap) to cover the observed ~2600-cycle
// effective load latency.  exp2-domain math; r folded directly into ah2 and
// h-hh rebuilt from th (chain ~88 cyc, bit-compatible accuracy).
// ---------------------------------------------------------------------------
#define PF 16

__global__ __launch_bounds__(256) void bru_scan(
    const float* __restrict__ mz, const float* __restrict__ mr,
    const float* __restrict__ bz, const float* __restrict__ br,
    const float* __restrict__ bh,
    float* __restrict__ out)
{
    const int b = blockIdx.x;        // batch
    const int u = threadIdx.x;       // unit

    const size_t base = (size_t)b * T_TOT * U_DIM + u;
    const float* __restrict__ pz = g_proj + base;
    const float* __restrict__ pr = g_proj + (size_t)1 * M_TOT * U_DIM + base;
    const float* __restrict__ ph = g_proj + (size_t)2 * M_TOT * U_DIM + base;
    float* __restrict__ po = out + base;

    const float C2 = 2.8853900817779268f;    // 2*log2(e)
    const float CN = -1.4426950408889634f;   // -log2(e)

    const float mr2 = mr[u] * C2, br2 = br[u] * C2;   // r-path, exp2 domain
    const float mzn = mz[u] * CN, bzn = bz[u] * CN;   // z-path, exp2 domain
    const float bh2 = bh[u] * C2;                     // h-path, exp2 domain

    float qz[PF], qr[PF], qh[PF];
#pragma unroll
    for (int j = 0; j < PF; j++) {
        qz[j] = pz[(size_t)j * U_DIM];
        qr[j] = pr[(size_t)j * U_DIM];
        qh[j] = ph[(size_t)j * U_DIM];
    }

    float h = 0.0f;

#pragma unroll 1
    for (int t0 = 0; t0 < T_TOT - PF; t0 += PF) {
#pragma unroll
        for (int j = 0; j < PF; j++) {
            const float vz = qz[j], vr = qr[j], vh = qh[j];
            // prefetch step t0 + j + PF (never OOB in this loop)
            qz[j] = pz[(size_t)(j + PF) * U_DIM];
            qr[j] = pr[(size_t)(j + PF) * U_DIM];
            qh[j] = ph[(size_t)(j + PF) * U_DIM];

            // off-chain precomputes (depend only on h, run under the MUFUs)
            const float hs   = h * C2;                       // h * 2log2e
            const float hbase= fmaf(vh, C2, bh2);            // xh in exp2 domain
            const float pre2 = fmaf(2.0f, hs, hbase);        // 2hs + base
            const float hm1  = h - 1.0f;

            // r-path: tr = 1/(exp2(ar2)+1);  r = 2 - 2tr (folded into ah2)
            const float ar2 = fmaf(h, mr2, fmaf(vr, C2, br2));
            const float tr  = rcpa(ex2a(ar2) + 1.0f);

            // z-path (parallel): z = 1/(1+exp2(azn))
            const float azn = fmaf(h, mzn, fmaf(vz, CN, bzn));
            const float z   = rcpa(ex2a(azn) + 1.0f);

            // h-path: ah2 = r*hs + hbase = pre2 - 2*tr*hs
            const float ah2 = fmaf(-2.0f * tr, hs, pre2);
            const float th  = rcpa(ex2a(ah2) + 1.0f);
            const float hh  = fmaf(-2.0f, th, 1.0f);         // tanh
            const float d   = fmaf(2.0f, th, hm1);           // h - hh

            h = fmaf(z, d, hh);
            po[(size_t)j * U_DIM] = h;
        }
        pz += PF * U_DIM; pr += PF * U_DIM; ph += PF * U_DIM; po += PF * U_DIM;
    }

    // tail: last PF steps, no prefetch
#pragma unroll
    for (int j = 0; j < PF; j++) {
        const float hs   = h * C2;
        const float hbase= fmaf(qh[j], C2, bh2);
        const float pre2 = fmaf(2.0f, hs, hbase);
        const float hm1  = h - 1.0f;

        const float ar2 = fmaf(h, mr2, fmaf(qr[j], C2, br2));
        const float tr  = rcpa(ex2a(ar2) + 1.0f);

        const float azn = fmaf(h, mzn, fmaf(qz[j], CN, bzn));
        const float z   = rcpa(ex2a(azn) + 1.0f);

        const float ah2 = fmaf(-2.0f * tr, hs, pre2);
        const float th  = rcpa(ex2a(ah2) + 1.0f);
        const float hh  = fmaf(-2.0f, th, 1.0f);
        const float d   = fmaf(2.0f, th, hm1);

        h = fmaf(z, d, hh);
        po[(size_t)j * U_DIM] = h;
    }
}

// ---------------------------------------------------------------------------
extern "C" void kernel_launch(void* const* d_in, const int* in_sizes, int n_in,
                              void* d_out, int out_size)
{
    const float* x  = (const float*)d_in[0];
    const float* kz = (const float*)d_in[1];
    const float* kr = (const float*)d_in[2];
    const float* kh = (const float*)d_in[3];
    const float* mz = (const float*)d_in[4];
    const float* mr = (const float*)d_in[5];
    const float* bz = (const float*)d_in[6];
    const float* br = (const float*)d_in[7];
    const float* bh = (const float*)d_in[8];
    float* out = (float*)d_out;

    cudaFuncSetAttribute(bru_gemm_mma, cudaFuncAttributeMaxDynamicSharedMemorySize, SMEM_SZ);

    bru_wprep<<<768, 256>>>(kz, kr, kh);
    dim3 gg(6, M_TOT / BM);
    bru_gemm_mma<<<gg, 256, SMEM_SZ>>>(x);
    bru_scan<<<B_TOT, 256>>>(mz, mr, bz, br, bh, out);
}